// round 9
// baseline (speedup 1.0000x reference)
#include <cuda_runtime.h>
#include <cuda_fp16.h>
#include <cstdint>
#include <cstddef>

// ---------------------------------------------------------------------------
// LMPNN encoder: B=8192, N=9, D=1024, H=4096; terms [2,4,6,8]:
//   agg[t] as linear combos of node slices; out[t] = relu(agg@W1+b1)@W2+b2.
//
// Round-8 result: fp16 m16n8k16 GEMM @ 335 TF/s, smem-bandwidth/issue bound
// (64x32 warp tile = 10.7 MAC/B). Round 9: 64x64 warp tiles (16 MAC/B, smem
// ceiling == HMMA peak) + ldmatrix.x4 fragment loads (3x fewer load instrs,
// 512B/instr). CTA 128x256x64, 8 warps, 3-stage cp.async.
// ---------------------------------------------------------------------------

namespace {
constexpr int B_N   = 8192;
constexpr int NODES = 9;
constexpr int D_DIM = 1024;
constexpr int H_DIM = 4096;
constexpr int TERMS = 4;
constexpr int M_TOT = TERMS * B_N;  // 32768

constexpr int BM = 128, BN = 256, BK = 64;    // BK in fp16 elements
constexpr int STAGES = 3;
constexpr int S_STRIDE = 72;                  // halves; 144B rows, bank-clean
constexpr int AS_H = BM * S_STRIDE;           // 9216 halves
constexpr int BS_H = BN * S_STRIDE;           // 18432 halves
constexpr int STAGE_H = AS_H + BS_H;          // 27648 halves = 55296 B
constexpr int STAGE_B = STAGE_H * 2;
constexpr int SMEM_BYTES = STAGES * STAGE_B;  // 165888 B
}

// Scratch (allocation-free rule: __device__ globals)
__device__ __half g_agg[(size_t)TERMS * B_N * D_DIM];   // 64 MB fp16
__device__ __half g_hid[(size_t)TERMS * B_N * H_DIM];   // 256 MB fp16
__device__ __half g_w1t[(size_t)H_DIM * D_DIM];         // W1^T [H,D] fp16
__device__ __half g_w2t[(size_t)D_DIM * H_DIM];         // W2^T [D,H] fp16

// ---------------------------------------------------------------------------
// Aggregation: one thread per (b, 4 channels); fp16 outputs.
// ---------------------------------------------------------------------------
__global__ void agg_kernel(const float* __restrict__ emb) {
    constexpr int KV = D_DIM / 4;
    size_t idx = (size_t)blockIdx.x * blockDim.x + threadIdx.x;
    if (idx >= (size_t)B_N * KV) return;
    int b  = (int)(idx / KV);
    int kv = (int)(idx % KV);

    const float4* e4p = reinterpret_cast<const float4*>(emb);
    size_t base = ((size_t)b * NODES) * KV + kv;
    float4 n2 = e4p[base + 2*KV];
    float4 n3 = e4p[base + 3*KV];
    float4 n4 = e4p[base + 4*KV];
    float4 n5 = e4p[base + 5*KV];
    float4 n6 = e4p[base + 6*KV];
    float4 n7 = e4p[base + 7*KV];
    float4 n8 = e4p[base + 8*KV];

    __half2* A = reinterpret_cast<__half2*>(g_agg);
    size_t tstride = (size_t)B_N * KV;   // in float4 units
    size_t o = (size_t)b * KV + kv;

    {   // t=2: 0.1*e2 - 3*e3 + 3*e4
        size_t h = (o + 0 * tstride) * 2;
        A[h]     = __floats2half2_rn(0.1f*n2.x - 3.f*n3.x + 3.f*n4.x,
                                     0.1f*n2.y - 3.f*n3.y + 3.f*n4.y);
        A[h + 1] = __floats2half2_rn(0.1f*n2.z - 3.f*n3.z + 3.f*n4.z,
                                     0.1f*n2.w - 3.f*n3.w + 3.f*n4.w);
    }
    {   // t=4: 3*(e2+e3+e6-e5) + 0.1*e4
        size_t h = (o + 1 * tstride) * 2;
        A[h]     = __floats2half2_rn(3.f*(n2.x+n3.x+n6.x-n5.x) + 0.1f*n4.x,
                                     3.f*(n2.y+n3.y+n6.y-n5.y) + 0.1f*n4.y);
        A[h + 1] = __floats2half2_rn(3.f*(n2.z+n3.z+n6.z-n5.z) + 0.1f*n4.z,
                                     3.f*(n2.w+n3.w+n6.w-n5.w) + 0.1f*n4.w);
    }
    {   // t=6: 3*(e4+e5+e8-e7) + 0.1*e6
        size_t h = (o + 2 * tstride) * 2;
        A[h]     = __floats2half2_rn(3.f*(n4.x+n5.x+n8.x-n7.x) + 0.1f*n6.x,
                                     3.f*(n4.y+n5.y+n8.y-n7.y) + 0.1f*n6.y);
        A[h + 1] = __floats2half2_rn(3.f*(n4.z+n5.z+n8.z-n7.z) + 0.1f*n6.z,
                                     3.f*(n4.w+n5.w+n8.w-n7.w) + 0.1f*n6.w);
    }
    {   // t=8: 3*(e6+e7) + 0.1*e8
        size_t h = (o + 3 * tstride) * 2;
        A[h]     = __floats2half2_rn(3.f*(n6.x+n7.x) + 0.1f*n8.x,
                                     3.f*(n6.y+n7.y) + 0.1f*n8.y);
        A[h + 1] = __floats2half2_rn(3.f*(n6.z+n7.z) + 0.1f*n8.z,
                                     3.f*(n6.w+n7.w) + 0.1f*n8.w);
    }
}

// ---------------------------------------------------------------------------
// Transpose + fp16 round: in[R][C] f32 -> out[C][R] fp16
// ---------------------------------------------------------------------------
__global__ void transpose_half(const float* __restrict__ in,
                               __half* __restrict__ out, int R, int C) {
    __shared__ float t[32][33];
    const int c0 = blockIdx.x * 32, r0 = blockIdx.y * 32;
    const int x = threadIdx.x, y = threadIdx.y;   // block (32, 8)
    #pragma unroll
    for (int dy = 0; dy < 32; dy += 8)
        t[y + dy][x] = in[(size_t)(r0 + y + dy) * C + c0 + x];
    __syncthreads();
    #pragma unroll
    for (int dy = 0; dy < 32; dy += 8)
        out[(size_t)(c0 + y + dy) * R + r0 + x] = __float2half_rn(t[x][y + dy]);
}

// ---------------------------------------------------------------------------
// ldmatrix.x4 helper
// ---------------------------------------------------------------------------
__device__ __forceinline__ void ldsm_x4(unsigned& r0, unsigned& r1,
                                        unsigned& r2, unsigned& r3,
                                        unsigned addr) {
    asm volatile(
        "ldmatrix.sync.aligned.m8n8.x4.shared.b16 {%0,%1,%2,%3}, [%4];\n"
        : "=r"(r0), "=r"(r1), "=r"(r2), "=r"(r3) : "r"(addr));
}

// ---------------------------------------------------------------------------
// FP16 tensor-core GEMM: C[M,N] = op(A[M,K] @ Bt[N,K]^T + bias[N])
//   A [M,K] fp16 row-major; Bt [N,K] fp16 row-major (pre-transposed weights).
//   CTA 128x256x64, 256 threads = 8 warps (2x4), warp tile 64x64,
//   mma.sync.m16n8k16.f16.f32, ldmatrix.x4 frags, 3-stage cp.async ring.
//   FUSED: relu + fp16 out (feeds GEMM2); else float out.
// ---------------------------------------------------------------------------
template <bool FUSED>
__global__ void __launch_bounds__(256, 1)
gemm_fp16(const __half* __restrict__ A, const __half* __restrict__ Bt,
          const float* __restrict__ bias, void* __restrict__ Cv,
          int M, int N, int K)
{
    extern __shared__ __half smem[];
    const unsigned smem_u32 = (unsigned)__cvta_generic_to_shared(smem);

    const int tid  = threadIdx.x;
    const int lane = tid & 31;
    const int warp = tid >> 5;          // 0..7
    const int warp_m = warp >> 2;       // 0..1 (64 rows each)
    const int warp_n = warp & 3;        // 0..3 (64 cols each)
    const int g  = lane >> 2;           // 0..7
    const int tg = lane & 3;            // 0..3
    const int m_cta = blockIdx.y * BM;
    const int n_cta = blockIdx.x * BN;

    const __half* Ag = A + (size_t)m_cta * K;
    const __half* Bg = Bt + (size_t)n_cta * K;

    // ldmatrix lane-address components (bytes, relative to operand base):
    // A x4: lanes 0-7 rows m0..+7 @k0 | 8-15 rows m0+8..+15 @k0
    //       | 16-23 rows m0..+7 @k+8 | 24-31 rows m0+8..+15 @k+8
    const int a_lrow = lane & 15;
    const int a_lk8  = (lane >> 4) * 8;
    // B x4 (per 16-n pair): 0-7 rows n0..+7 @k0 | 8-15 rows n0..+7 @k+8
    //       | 16-23 rows n0+8..+15 @k0 | 24-31 rows n0+8..+15 @k+8
    const int b_lrow = (lane & 7) + ((lane >> 4) * 8);
    const int b_lk8  = ((lane >> 3) & 1) * 8;

    // Loader: A 1024 + B 2048 16B-chunks; 12 per thread.
    auto issue_tile = [&](int kt, int s) {
        const int k0 = kt * BK;
        __half* As = smem + s * STAGE_H;
        __half* Bs = As + AS_H;
        #pragma unroll
        for (int i = 0; i < 4; ++i) {
            int c = tid + i * 256;
            int row = c >> 3, kq = c & 7;
            const __half* src = Ag + (size_t)row * K + k0 + kq * 8;
            unsigned dst = (unsigned)__cvta_generic_to_shared(
                As + row * S_STRIDE + kq * 8);
            asm volatile("cp.async.cg.shared.global [%0], [%1], 16;\n"
                         :: "r"(dst), "l"(src));
        }
        #pragma unroll
        for (int i = 0; i < 8; ++i) {
            int c = tid + i * 256;
            int row = c >> 3, kq = c & 7;
            const __half* src = Bg + (size_t)row * K + k0 + kq * 8;
            unsigned dst = (unsigned)__cvta_generic_to_shared(
                Bs + row * S_STRIDE + kq * 8);
            asm volatile("cp.async.cg.shared.global [%0], [%1], 16;\n"
                         :: "r"(dst), "l"(src));
        }
        asm volatile("cp.async.commit_group;\n");
    };

    float acc[4][8][4];
    #pragma unroll
    for (int mt = 0; mt < 4; ++mt)
        #pragma unroll
        for (int nt = 0; nt < 8; ++nt)
            #pragma unroll
            for (int r = 0; r < 4; ++r) acc[mt][nt][r] = 0.0f;

    const int KT = K / BK;
    issue_tile(0, 0);
    issue_tile(1, 1);

    for (int kt = 0; kt < KT; ++kt) {
        if (kt + 2 < KT) issue_tile(kt + 2, (kt + 2) % STAGES);
        const int loaded = (kt + 2 < KT) ? kt + 2 : KT - 1;
        const int pend = loaded - kt;
        if (pend >= 2)      asm volatile("cp.async.wait_group 2;\n" ::: "memory");
        else if (pend == 1) asm volatile("cp.async.wait_group 1;\n" ::: "memory");
        else                asm volatile("cp.async.wait_group 0;\n" ::: "memory");
        __syncthreads();

        const unsigned as_u32 = smem_u32 + (kt % STAGES) * STAGE_B;
        const unsigned bs_u32 = as_u32 + AS_H * 2;
        // lane base addresses (bytes)
        const unsigned a_base = as_u32 +
            ((warp_m * 64 + a_lrow) * S_STRIDE + a_lk8) * 2;
        const unsigned b_base = bs_u32 +
            ((warp_n * 64 + b_lrow) * S_STRIDE + b_lk8) * 2;

        #pragma unroll
        for (int ks = 0; ks < 4; ++ks) {          // 4 x k16 steps
            const unsigned kofs = ks * 32;        // 16 halves = 32 B
            unsigned af[4][4];
            #pragma unroll
            for (int mt = 0; mt < 4; ++mt)
                ldsm_x4(af[mt][0], af[mt][1], af[mt][2], af[mt][3],
                        a_base + mt * 16 * S_STRIDE * 2 + kofs);
            unsigned bf[8][2];
            #pragma unroll
            for (int p = 0; p < 4; ++p)           // 4 pairs of nt
                ldsm_x4(bf[2*p][0], bf[2*p][1], bf[2*p+1][0], bf[2*p+1][1],
                        b_base + p * 16 * S_STRIDE * 2 + kofs);
            #pragma unroll
            for (int mt = 0; mt < 4; ++mt)
                #pragma unroll
                for (int nt = 0; nt < 8; ++nt) {
                    asm volatile(
                        "mma.sync.aligned.m16n8k16.row.col.f32.f16.f16.f32 "
                        "{%0,%1,%2,%3}, {%4,%5,%6,%7}, {%8,%9}, {%0,%1,%2,%3};\n"
                        : "+f"(acc[mt][nt][0]), "+f"(acc[mt][nt][1]),
                          "+f"(acc[mt][nt][2]), "+f"(acc[mt][nt][3])
                        : "r"(af[mt][0]), "r"(af[mt][1]),
                          "r"(af[mt][2]), "r"(af[mt][3]),
                          "r"(bf[nt][0]), "r"(bf[nt][1]));
                }
        }
        __syncthreads();
    }

    // Epilogue
    #pragma unroll
    for (int mt = 0; mt < 4; ++mt) {
        const int r0 = m_cta + warp_m * 64 + mt * 16 + g;
        #pragma unroll
        for (int nt = 0; nt < 8; ++nt) {
            const int col = n_cta + warp_n * 64 + nt * 8 + tg * 2;
            const float bv0 = bias[col], bv1 = bias[col + 1];
            float v0 = acc[mt][nt][0] + bv0;
            float v1 = acc[mt][nt][1] + bv1;
            float v2 = acc[mt][nt][2] + bv0;
            float v3 = acc[mt][nt][3] + bv1;
            if (FUSED) {
                __half* C = reinterpret_cast<__half*>(Cv);
                *reinterpret_cast<__half2*>(C + (size_t)r0 * N + col) =
                    __floats2half2_rn(fmaxf(v0, 0.0f), fmaxf(v1, 0.0f));
                *reinterpret_cast<__half2*>(C + (size_t)(r0 + 8) * N + col) =
                    __floats2half2_rn(fmaxf(v2, 0.0f), fmaxf(v3, 0.0f));
            } else {
                float* C = reinterpret_cast<float*>(Cv);
                *reinterpret_cast<float2*>(C + (size_t)r0 * N + col) =
                    make_float2(v0, v1);
                *reinterpret_cast<float2*>(C + (size_t)(r0 + 8) * N + col) =
                    make_float2(v2, v3);
            }
        }
    }
}

// ---------------------------------------------------------------------------
// Launch
// ---------------------------------------------------------------------------
extern "C" void kernel_launch(void* const* d_in, const int* in_sizes, int n_in,
                              void* d_out, int out_size)
{
    (void)in_sizes; (void)n_in; (void)out_size;
    const float* emb = (const float*)d_in[0];
    const float* W1  = (const float*)d_in[1];
    const float* b1  = (const float*)d_in[2];
    const float* W2  = (const float*)d_in[3];
    const float* b2  = (const float*)d_in[4];
    float* out = (float*)d_out;

    cudaFuncSetAttribute(gemm_fp16<true>,
                         cudaFuncAttributeMaxDynamicSharedMemorySize, SMEM_BYTES);
    cudaFuncSetAttribute(gemm_fp16<false>,
                         cudaFuncAttributeMaxDynamicSharedMemorySize, SMEM_BYTES);

    void *pA = nullptr, *pH = nullptr, *pW1 = nullptr, *pW2 = nullptr;
    cudaGetSymbolAddress(&pA, g_agg);
    cudaGetSymbolAddress(&pH, g_hid);
    cudaGetSymbolAddress(&pW1, g_w1t);
    cudaGetSymbolAddress(&pW2, g_w2t);
    __half* agg = (__half*)pA;
    __half* hid = (__half*)pH;
    __half* w1t = (__half*)pW1;
    __half* w2t = (__half*)pW2;

    // 1) Aggregation -> fp16: (4, 8192, 1024)
    agg_kernel<<<B_N * (D_DIM / 4) / 256, 256>>>(emb);

    // 1b) Weights -> [N,K] fp16
    transpose_half<<<dim3(H_DIM / 32, D_DIM / 32), dim3(32, 8)>>>(
        W1, w1t, D_DIM, H_DIM);   // W1 [D,H] -> w1t [H,D]
    transpose_half<<<dim3(D_DIM / 32, H_DIM / 32), dim3(32, 8)>>>(
        W2, w2t, H_DIM, D_DIM);   // W2 [H,D] -> w2t [D,H]

    // 2) hid = fp16(relu(agg @ W1 + b1)): M=32768, N=4096, K=1024
    {
        dim3 grid(H_DIM / BN, M_TOT / BM);   // (16, 256)
        gemm_fp16<true><<<grid, 256, SMEM_BYTES>>>(agg, w1t, b1, hid,
                                                   M_TOT, H_DIM, D_DIM);
    }

    // 3) out = hid @ W2 + b2: M=32768, N=1024, K=4096 -> (4,8192,1024)
    {
        dim3 grid(D_DIM / BN, M_TOT / BM);   // (4, 256)
        gemm_fp16<false><<<grid, 256, SMEM_BYTES>>>(hid, w2t, b2, out,
                                                    M_TOT, D_DIM, H_DIM);
    }
}

// round 13
// speedup vs baseline: 1.6344x; 1.6344x over previous
#include <cuda_runtime.h>
#include <cuda_fp16.h>
#include <cstdint>
#include <cstddef>

// ---------------------------------------------------------------------------
// LMPNN encoder: B=8192, N=9, D=1024, H=4096; terms [2,4,6,8]:
//   agg[t] as linear combos of node slices; out[t] = relu(agg@W1+b1)@W2+b2.
//
// Round-8 (1679us, PROVEN): fp16 m16n8k16, CTA 128x128x64, warp tile 64x32,
//   regs=128, 2 CTA/SM. Round-9 (2527us): 64x64 warp tile -> regs=238,
//   occ 12.5%, regression; but its ldmatrix.x4 addressing was validated.
// Round 10 = round-8 config + LDSM fragment loads (24 LDS -> 6 LDSM per
//   ks-step, same fragment regs, same occupancy).
// ---------------------------------------------------------------------------

namespace {
constexpr int B_N   = 8192;
constexpr int NODES = 9;
constexpr int D_DIM = 1024;
constexpr int H_DIM = 4096;
constexpr int TERMS = 4;
constexpr int M_TOT = TERMS * B_N;  // 32768

constexpr int BM = 128, BN = 128, BK = 64;    // BK in fp16 elements
constexpr int STAGES = 3;
constexpr int S_STRIDE = 72;                  // halves; 144B rows, bank-clean
constexpr int AS_H = BM * S_STRIDE;           // 9216 halves
constexpr int BS_H = BN * S_STRIDE;           // 9216 halves
constexpr int STAGE_H = AS_H + BS_H;          // 18432 halves = 36864 B
constexpr int STAGE_B = STAGE_H * 2;
constexpr int SMEM_BYTES = STAGES * STAGE_B;  // 110592 B (2 CTA/SM fits 228KB)
}

// Scratch (allocation-free rule: __device__ globals)
__device__ __half g_agg[(size_t)TERMS * B_N * D_DIM];   // 64 MB fp16
__device__ __half g_hid[(size_t)TERMS * B_N * H_DIM];   // 256 MB fp16
__device__ __half g_w1t[(size_t)H_DIM * D_DIM];         // W1^T [H,D] fp16
__device__ __half g_w2t[(size_t)D_DIM * H_DIM];         // W2^T [D,H] fp16

// ---------------------------------------------------------------------------
// Aggregation: one thread per (b, 4 channels); fp16 outputs.
// ---------------------------------------------------------------------------
__global__ void agg_kernel(const float* __restrict__ emb) {
    constexpr int KV = D_DIM / 4;
    size_t idx = (size_t)blockIdx.x * blockDim.x + threadIdx.x;
    if (idx >= (size_t)B_N * KV) return;
    int b  = (int)(idx / KV);
    int kv = (int)(idx % KV);

    const float4* e4p = reinterpret_cast<const float4*>(emb);
    size_t base = ((size_t)b * NODES) * KV + kv;
    float4 n2 = e4p[base + 2*KV];
    float4 n3 = e4p[base + 3*KV];
    float4 n4 = e4p[base + 4*KV];
    float4 n5 = e4p[base + 5*KV];
    float4 n6 = e4p[base + 6*KV];
    float4 n7 = e4p[base + 7*KV];
    float4 n8 = e4p[base + 8*KV];

    __half2* A = reinterpret_cast<__half2*>(g_agg);
    size_t tstride = (size_t)B_N * KV;   // in float4 units
    size_t o = (size_t)b * KV + kv;

    {   // t=2: 0.1*e2 - 3*e3 + 3*e4
        size_t h = (o + 0 * tstride) * 2;
        A[h]     = __floats2half2_rn(0.1f*n2.x - 3.f*n3.x + 3.f*n4.x,
                                     0.1f*n2.y - 3.f*n3.y + 3.f*n4.y);
        A[h + 1] = __floats2half2_rn(0.1f*n2.z - 3.f*n3.z + 3.f*n4.z,
                                     0.1f*n2.w - 3.f*n3.w + 3.f*n4.w);
    }
    {   // t=4: 3*(e2+e3+e6-e5) + 0.1*e4
        size_t h = (o + 1 * tstride) * 2;
        A[h]     = __floats2half2_rn(3.f*(n2.x+n3.x+n6.x-n5.x) + 0.1f*n4.x,
                                     3.f*(n2.y+n3.y+n6.y-n5.y) + 0.1f*n4.y);
        A[h + 1] = __floats2half2_rn(3.f*(n2.z+n3.z+n6.z-n5.z) + 0.1f*n4.z,
                                     3.f*(n2.w+n3.w+n6.w-n5.w) + 0.1f*n4.w);
    }
    {   // t=6: 3*(e4+e5+e8-e7) + 0.1*e6
        size_t h = (o + 2 * tstride) * 2;
        A[h]     = __floats2half2_rn(3.f*(n4.x+n5.x+n8.x-n7.x) + 0.1f*n6.x,
                                     3.f*(n4.y+n5.y+n8.y-n7.y) + 0.1f*n6.y);
        A[h + 1] = __floats2half2_rn(3.f*(n4.z+n5.z+n8.z-n7.z) + 0.1f*n6.z,
                                     3.f*(n4.w+n5.w+n8.w-n7.w) + 0.1f*n6.w);
    }
    {   // t=8: 3*(e6+e7) + 0.1*e8
        size_t h = (o + 3 * tstride) * 2;
        A[h]     = __floats2half2_rn(3.f*(n6.x+n7.x) + 0.1f*n8.x,
                                     3.f*(n6.y+n7.y) + 0.1f*n8.y);
        A[h + 1] = __floats2half2_rn(3.f*(n6.z+n7.z) + 0.1f*n8.z,
                                     3.f*(n6.w+n7.w) + 0.1f*n8.w);
    }
}

// ---------------------------------------------------------------------------
// Transpose + fp16 round: in[R][C] f32 -> out[C][R] fp16
// ---------------------------------------------------------------------------
__global__ void transpose_half(const float* __restrict__ in,
                               __half* __restrict__ out, int R, int C) {
    __shared__ float t[32][33];
    const int c0 = blockIdx.x * 32, r0 = blockIdx.y * 32;
    const int x = threadIdx.x, y = threadIdx.y;   // block (32, 8)
    #pragma unroll
    for (int dy = 0; dy < 32; dy += 8)
        t[y + dy][x] = in[(size_t)(r0 + y + dy) * C + c0 + x];
    __syncthreads();
    #pragma unroll
    for (int dy = 0; dy < 32; dy += 8)
        out[(size_t)(c0 + y + dy) * R + r0 + x] = __float2half_rn(t[x][y + dy]);
}

// ---------------------------------------------------------------------------
// ldmatrix.x4 helper
// ---------------------------------------------------------------------------
__device__ __forceinline__ void ldsm_x4(unsigned& r0, unsigned& r1,
                                        unsigned& r2, unsigned& r3,
                                        unsigned addr) {
    asm volatile(
        "ldmatrix.sync.aligned.m8n8.x4.shared.b16 {%0,%1,%2,%3}, [%4];\n"
        : "=r"(r0), "=r"(r1), "=r"(r2), "=r"(r3) : "r"(addr));
}

// ---------------------------------------------------------------------------
// FP16 tensor-core GEMM: C[M,N] = op(A[M,K] @ Bt[N,K]^T + bias[N])
//   A [M,K] fp16 row-major; Bt [N,K] fp16 row-major (pre-transposed weights).
//   CTA 128x128x64, 256 threads = 8 warps (2x4), warp tile 64x32,
//   mma.sync.m16n8k16.f16.f32, ldmatrix.x4 frags, 3-stage cp.async ring.
//   FUSED: relu + fp16 out (feeds GEMM2); else float out.
// ---------------------------------------------------------------------------
template <bool FUSED>
__global__ void __launch_bounds__(256, 2)
gemm_fp16(const __half* __restrict__ A, const __half* __restrict__ Bt,
          const float* __restrict__ bias, void* __restrict__ Cv,
          int M, int N, int K)
{
    extern __shared__ __half smem[];
    const unsigned smem_u32 = (unsigned)__cvta_generic_to_shared(smem);

    const int tid  = threadIdx.x;
    const int lane = tid & 31;
    const int warp = tid >> 5;          // 0..7
    const int warp_m = warp >> 2;       // 0..1 (64 rows each)
    const int warp_n = warp & 3;        // 0..3 (32 cols each)
    const int g  = lane >> 2;           // 0..7
    const int tg = lane & 3;            // 0..3
    const int m_cta = blockIdx.y * BM;
    const int n_cta = blockIdx.x * BN;

    const __half* Ag = A + (size_t)m_cta * K;
    const __half* Bg = Bt + (size_t)n_cta * K;

    // ldmatrix lane-address components (validated in round 9):
    // A x4: lanes 0-7 rows m+0..7 @k0 | 8-15 rows m+8..15 @k0
    //       | 16-23 rows m+0..7 @k8 | 24-31 rows m+8..15 @k8
    const int a_lrow = lane & 15;
    const int a_lk8  = (lane >> 4) * 8;
    // B x4 (16 n-rows): 0-7 n+0..7 @k0 | 8-15 n+0..7 @k8
    //       | 16-23 n+8..15 @k0 | 24-31 n+8..15 @k8
    const int b_lrow = (lane & 7) + ((lane >> 4) * 8);
    const int b_lk8  = ((lane >> 3) & 1) * 8;

    // Loader: per operand tile 128 rows x 8 x 16B chunks; 4 per thread each.
    auto issue_tile = [&](int kt, int s) {
        const int k0 = kt * BK;
        __half* As = smem + s * STAGE_H;
        __half* Bs = As + AS_H;
        #pragma unroll
        for (int i = 0; i < 4; ++i) {
            int c = tid + i * 256;
            int row = c >> 3, kq = c & 7;
            const __half* src = Ag + (size_t)row * K + k0 + kq * 8;
            unsigned dst = (unsigned)__cvta_generic_to_shared(
                As + row * S_STRIDE + kq * 8);
            asm volatile("cp.async.cg.shared.global [%0], [%1], 16;\n"
                         :: "r"(dst), "l"(src));
        }
        #pragma unroll
        for (int i = 0; i < 4; ++i) {
            int c = tid + i * 256;
            int row = c >> 3, kq = c & 7;
            const __half* src = Bg + (size_t)row * K + k0 + kq * 8;
            unsigned dst = (unsigned)__cvta_generic_to_shared(
                Bs + row * S_STRIDE + kq * 8);
            asm volatile("cp.async.cg.shared.global [%0], [%1], 16;\n"
                         :: "r"(dst), "l"(src));
        }
        asm volatile("cp.async.commit_group;\n");
    };

    float acc[4][4][4];
    #pragma unroll
    for (int mt = 0; mt < 4; ++mt)
        #pragma unroll
        for (int nt = 0; nt < 4; ++nt)
            #pragma unroll
            for (int r = 0; r < 4; ++r) acc[mt][nt][r] = 0.0f;

    const int KT = K / BK;
    issue_tile(0, 0);
    issue_tile(1, 1);

    for (int kt = 0; kt < KT; ++kt) {
        if (kt + 2 < KT) issue_tile(kt + 2, (kt + 2) % STAGES);
        const int loaded = (kt + 2 < KT) ? kt + 2 : KT - 1;
        const int pend = loaded - kt;
        if (pend >= 2)      asm volatile("cp.async.wait_group 2;\n" ::: "memory");
        else if (pend == 1) asm volatile("cp.async.wait_group 1;\n" ::: "memory");
        else                asm volatile("cp.async.wait_group 0;\n" ::: "memory");
        __syncthreads();

        const unsigned as_u32 = smem_u32 + (kt % STAGES) * STAGE_B;
        const unsigned bs_u32 = as_u32 + AS_H * 2;
        const unsigned a_base = as_u32 +
            ((warp_m * 64 + a_lrow) * S_STRIDE + a_lk8) * 2;
        const unsigned b_base = bs_u32 +
            ((warp_n * 32 + b_lrow) * S_STRIDE + b_lk8) * 2;

        #pragma unroll
        for (int ks = 0; ks < 4; ++ks) {          // 4 x k16 steps
            const unsigned kofs = ks * 32;        // 16 halves = 32 B
            unsigned af[4][4];
            #pragma unroll
            for (int mt = 0; mt < 4; ++mt)
                ldsm_x4(af[mt][0], af[mt][1], af[mt][2], af[mt][3],
                        a_base + mt * 16 * S_STRIDE * 2 + kofs);
            unsigned bf[4][2];
            #pragma unroll
            for (int p = 0; p < 2; ++p)           // 2 pairs of nt
                ldsm_x4(bf[2*p][0], bf[2*p][1], bf[2*p+1][0], bf[2*p+1][1],
                        b_base + p * 16 * S_STRIDE * 2 + kofs);
            #pragma unroll
            for (int mt = 0; mt < 4; ++mt)
                #pragma unroll
                for (int nt = 0; nt < 4; ++nt) {
                    asm volatile(
                        "mma.sync.aligned.m16n8k16.row.col.f32.f16.f16.f32 "
                        "{%0,%1,%2,%3}, {%4,%5,%6,%7}, {%8,%9}, {%0,%1,%2,%3};\n"
                        : "+f"(acc[mt][nt][0]), "+f"(acc[mt][nt][1]),
                          "+f"(acc[mt][nt][2]), "+f"(acc[mt][nt][3])
                        : "r"(af[mt][0]), "r"(af[mt][1]),
                          "r"(af[mt][2]), "r"(af[mt][3]),
                          "r"(bf[nt][0]), "r"(bf[nt][1]));
                }
        }
        __syncthreads();
    }

    // Epilogue
    #pragma unroll
    for (int mt = 0; mt < 4; ++mt) {
        const int r0 = m_cta + warp_m * 64 + mt * 16 + g;
        #pragma unroll
        for (int nt = 0; nt < 4; ++nt) {
            const int col = n_cta + warp_n * 32 + nt * 8 + tg * 2;
            const float bv0 = bias[col], bv1 = bias[col + 1];
            float v0 = acc[mt][nt][0] + bv0;
            float v1 = acc[mt][nt][1] + bv1;
            float v2 = acc[mt][nt][2] + bv0;
            float v3 = acc[mt][nt][3] + bv1;
            if (FUSED) {
                __half* C = reinterpret_cast<__half*>(Cv);
                *reinterpret_cast<__half2*>(C + (size_t)r0 * N + col) =
                    __floats2half2_rn(fmaxf(v0, 0.0f), fmaxf(v1, 0.0f));
                *reinterpret_cast<__half2*>(C + (size_t)(r0 + 8) * N + col) =
                    __floats2half2_rn(fmaxf(v2, 0.0f), fmaxf(v3, 0.0f));
            } else {
                float* C = reinterpret_cast<float*>(Cv);
                *reinterpret_cast<float2*>(C + (size_t)r0 * N + col) =
                    make_float2(v0, v1);
                *reinterpret_cast<float2*>(C + (size_t)(r0 + 8) * N + col) =
                    make_float2(v2, v3);
            }
        }
    }
}

// ---------------------------------------------------------------------------
// Launch
// ---------------------------------------------------------------------------
extern "C" void kernel_launch(void* const* d_in, const int* in_sizes, int n_in,
                              void* d_out, int out_size)
{
    (void)in_sizes; (void)n_in; (void)out_size;
    const float* emb = (const float*)d_in[0];
    const float* W1  = (const float*)d_in[1];
    const float* b1  = (const float*)d_in[2];
    const float* W2  = (const float*)d_in[3];
    const float* b2  = (const float*)d_in[4];
    float* out = (float*)d_out;

    cudaFuncSetAttribute(gemm_fp16<true>,
                         cudaFuncAttributeMaxDynamicSharedMemorySize, SMEM_BYTES);
    cudaFuncSetAttribute(gemm_fp16<false>,
                         cudaFuncAttributeMaxDynamicSharedMemorySize, SMEM_BYTES);

    void *pA = nullptr, *pH = nullptr, *pW1 = nullptr, *pW2 = nullptr;
    cudaGetSymbolAddress(&pA, g_agg);
    cudaGetSymbolAddress(&pH, g_hid);
    cudaGetSymbolAddress(&pW1, g_w1t);
    cudaGetSymbolAddress(&pW2, g_w2t);
    __half* agg = (__half*)pA;
    __half* hid = (__half*)pH;
    __half* w1t = (__half*)pW1;
    __half* w2t = (__half*)pW2;

    // 1) Aggregation -> fp16: (4, 8192, 1024)
    agg_kernel<<<B_N * (D_DIM / 4) / 256, 256>>>(emb);

    // 1b) Weights -> [N,K] fp16
    transpose_half<<<dim3(H_DIM / 32, D_DIM / 32), dim3(32, 8)>>>(
        W1, w1t, D_DIM, H_DIM);   // W1 [D,H] -> w1t [H,D]
    transpose_half<<<dim3(D_DIM / 32, H_DIM / 32), dim3(32, 8)>>>(
        W2, w2t, H_DIM, D_DIM);   // W2 [H,D] -> w2t [D,H]

    // 2) hid = fp16(relu(agg @ W1 + b1)): M=32768, N=4096, K=1024
    {
        dim3 grid(H_DIM / BN, M_TOT / BM);   // (32, 256)
        gemm_fp16<true><<<grid, 256, SMEM_BYTES>>>(agg, w1t, b1, hid,
                                                   M_TOT, H_DIM, D_DIM);
    }

    // 3) out = hid @ W2 + b2: M=32768, N=1024, K=4096 -> (4,8192,1024)
    {
        dim3 grid(D_DIM / BN, M_TOT / BM);   // (8, 256)
        gemm_fp16<false><<<grid, 256, SMEM_BYTES>>>(hid, w2t, b2, out,
                                                    M_TOT, D_DIM, H_DIM);
    }
}

// round 17
// speedup vs baseline: 1.6431x; 1.0053x over previous
#include <cuda_runtime.h>
#include <cuda_fp16.h>
#include <cstdint>
#include <cstddef>

// ---------------------------------------------------------------------------
// LMPNN encoder: B=8192, N=9, D=1024, H=4096; terms [2,4,6,8]:
//   agg[t] as linear combos of node slices; out[t] = relu(agg@W1+b1)@W2+b2.
//
// Round-13 (1546us): fp16 m16n8k16, CTA 128x128x64, warp 64x32, LDSM frags,
//   regs=128, 2 CTA/SM. Profile: tensor 59.6%, crossbar 72%, issue 19.8%
//   => latency/overlap-bound, not bandwidth-bound.
// Round 14: single barrier per K-tile (wait -> sync -> issue -> compute),
//   B-frags-first + A-frag software pipelining across mt. No layout changes.
// ---------------------------------------------------------------------------

namespace {
constexpr int B_N   = 8192;
constexpr int NODES = 9;
constexpr int D_DIM = 1024;
constexpr int H_DIM = 4096;
constexpr int TERMS = 4;
constexpr int M_TOT = TERMS * B_N;  // 32768

constexpr int BM = 128, BN = 128, BK = 64;    // BK in fp16 elements
constexpr int STAGES = 3;
constexpr int S_STRIDE = 72;                  // halves; 144B rows, bank-clean
constexpr int AS_H = BM * S_STRIDE;           // 9216 halves
constexpr int BS_H = BN * S_STRIDE;           // 9216 halves
constexpr int STAGE_H = AS_H + BS_H;          // 18432 halves = 36864 B
constexpr int STAGE_B = STAGE_H * 2;
constexpr int SMEM_BYTES = STAGES * STAGE_B;  // 110592 B (2 CTA/SM fits 228KB)
}

// Scratch (allocation-free rule: __device__ globals)
__device__ __half g_agg[(size_t)TERMS * B_N * D_DIM];   // 64 MB fp16
__device__ __half g_hid[(size_t)TERMS * B_N * H_DIM];   // 256 MB fp16
__device__ __half g_w1t[(size_t)H_DIM * D_DIM];         // W1^T [H,D] fp16
__device__ __half g_w2t[(size_t)D_DIM * H_DIM];         // W2^T [D,H] fp16

// ---------------------------------------------------------------------------
// Aggregation: one thread per (b, 4 channels); fp16 outputs.
// ---------------------------------------------------------------------------
__global__ void agg_kernel(const float* __restrict__ emb) {
    constexpr int KV = D_DIM / 4;
    size_t idx = (size_t)blockIdx.x * blockDim.x + threadIdx.x;
    if (idx >= (size_t)B_N * KV) return;
    int b  = (int)(idx / KV);
    int kv = (int)(idx % KV);

    const float4* e4p = reinterpret_cast<const float4*>(emb);
    size_t base = ((size_t)b * NODES) * KV + kv;
    float4 n2 = e4p[base + 2*KV];
    float4 n3 = e4p[base + 3*KV];
    float4 n4 = e4p[base + 4*KV];
    float4 n5 = e4p[base + 5*KV];
    float4 n6 = e4p[base + 6*KV];
    float4 n7 = e4p[base + 7*KV];
    float4 n8 = e4p[base + 8*KV];

    __half2* A = reinterpret_cast<__half2*>(g_agg);
    size_t tstride = (size_t)B_N * KV;   // in float4 units
    size_t o = (size_t)b * KV + kv;

    {   // t=2: 0.1*e2 - 3*e3 + 3*e4
        size_t h = (o + 0 * tstride) * 2;
        A[h]     = __floats2half2_rn(0.1f*n2.x - 3.f*n3.x + 3.f*n4.x,
                                     0.1f*n2.y - 3.f*n3.y + 3.f*n4.y);
        A[h + 1] = __floats2half2_rn(0.1f*n2.z - 3.f*n3.z + 3.f*n4.z,
                                     0.1f*n2.w - 3.f*n3.w + 3.f*n4.w);
    }
    {   // t=4: 3*(e2+e3+e6-e5) + 0.1*e4
        size_t h = (o + 1 * tstride) * 2;
        A[h]     = __floats2half2_rn(3.f*(n2.x+n3.x+n6.x-n5.x) + 0.1f*n4.x,
                                     3.f*(n2.y+n3.y+n6.y-n5.y) + 0.1f*n4.y);
        A[h + 1] = __floats2half2_rn(3.f*(n2.z+n3.z+n6.z-n5.z) + 0.1f*n4.z,
                                     3.f*(n2.w+n3.w+n6.w-n5.w) + 0.1f*n4.w);
    }
    {   // t=6: 3*(e4+e5+e8-e7) + 0.1*e6
        size_t h = (o + 2 * tstride) * 2;
        A[h]     = __floats2half2_rn(3.f*(n4.x+n5.x+n8.x-n7.x) + 0.1f*n6.x,
                                     3.f*(n4.y+n5.y+n8.y-n7.y) + 0.1f*n6.y);
        A[h + 1] = __floats2half2_rn(3.f*(n4.z+n5.z+n8.z-n7.z) + 0.1f*n6.z,
                                     3.f*(n4.w+n5.w+n8.w-n7.w) + 0.1f*n6.w);
    }
    {   // t=8: 3*(e6+e7) + 0.1*e8
        size_t h = (o + 3 * tstride) * 2;
        A[h]     = __floats2half2_rn(3.f*(n6.x+n7.x) + 0.1f*n8.x,
                                     3.f*(n6.y+n7.y) + 0.1f*n8.y);
        A[h + 1] = __floats2half2_rn(3.f*(n6.z+n7.z) + 0.1f*n8.z,
                                     3.f*(n6.w+n7.w) + 0.1f*n8.w);
    }
}

// ---------------------------------------------------------------------------
// Transpose + fp16 round: in[R][C] f32 -> out[C][R] fp16
// ---------------------------------------------------------------------------
__global__ void transpose_half(const float* __restrict__ in,
                               __half* __restrict__ out, int R, int C) {
    __shared__ float t[32][33];
    const int c0 = blockIdx.x * 32, r0 = blockIdx.y * 32;
    const int x = threadIdx.x, y = threadIdx.y;   // block (32, 8)
    #pragma unroll
    for (int dy = 0; dy < 32; dy += 8)
        t[y + dy][x] = in[(size_t)(r0 + y + dy) * C + c0 + x];
    __syncthreads();
    #pragma unroll
    for (int dy = 0; dy < 32; dy += 8)
        out[(size_t)(c0 + y + dy) * R + r0 + x] = __float2half_rn(t[x][y + dy]);
}

// ---------------------------------------------------------------------------
// ldmatrix.x4 helper
// ---------------------------------------------------------------------------
__device__ __forceinline__ void ldsm_x4(unsigned& r0, unsigned& r1,
                                        unsigned& r2, unsigned& r3,
                                        unsigned addr) {
    asm volatile(
        "ldmatrix.sync.aligned.m8n8.x4.shared.b16 {%0,%1,%2,%3}, [%4];\n"
        : "=r"(r0), "=r"(r1), "=r"(r2), "=r"(r3) : "r"(addr));
}

// ---------------------------------------------------------------------------
// FP16 tensor-core GEMM: C[M,N] = op(A[M,K] @ Bt[N,K]^T + bias[N])
//   A [M,K] fp16 row-major; Bt [N,K] fp16 row-major (pre-transposed weights).
//   CTA 128x128x64, 256 threads = 8 warps (2x4), warp tile 64x32,
//   mma.sync.m16n8k16.f16.f32, ldmatrix.x4 frags, 3-stage cp.async ring,
//   ONE __syncthreads per K-tile (wait -> sync -> issue -> compute).
//   FUSED: relu + fp16 out (feeds GEMM2); else float out.
// ---------------------------------------------------------------------------
template <bool FUSED>
__global__ void __launch_bounds__(256, 2)
gemm_fp16(const __half* __restrict__ A, const __half* __restrict__ Bt,
          const float* __restrict__ bias, void* __restrict__ Cv,
          int M, int N, int K)
{
    extern __shared__ __half smem[];
    const unsigned smem_u32 = (unsigned)__cvta_generic_to_shared(smem);

    const int tid  = threadIdx.x;
    const int lane = tid & 31;
    const int warp = tid >> 5;          // 0..7
    const int warp_m = warp >> 2;       // 0..1 (64 rows each)
    const int warp_n = warp & 3;        // 0..3 (32 cols each)
    const int g  = lane >> 2;           // 0..7
    const int tg = lane & 3;            // 0..3
    const int m_cta = blockIdx.y * BM;
    const int n_cta = blockIdx.x * BN;

    const __half* Ag = A + (size_t)m_cta * K;
    const __half* Bg = Bt + (size_t)n_cta * K;

    // ldmatrix lane-address components (validated rounds 9/13):
    const int a_lrow = lane & 15;
    const int a_lk8  = (lane >> 4) * 8;
    const int b_lrow = (lane & 7) + ((lane >> 4) * 8);
    const int b_lk8  = ((lane >> 3) & 1) * 8;

    // Loader: per operand tile 128 rows x 8 x 16B chunks; 4 per thread each.
    auto issue_tile = [&](int kt, int s) {
        const int k0 = kt * BK;
        __half* As = smem + s * STAGE_H;
        __half* Bs = As + AS_H;
        #pragma unroll
        for (int i = 0; i < 4; ++i) {
            int c = tid + i * 256;
            int row = c >> 3, kq = c & 7;
            const __half* src = Ag + (size_t)row * K + k0 + kq * 8;
            unsigned dst = (unsigned)__cvta_generic_to_shared(
                As + row * S_STRIDE + kq * 8);
            asm volatile("cp.async.cg.shared.global [%0], [%1], 16;\n"
                         :: "r"(dst), "l"(src));
        }
        #pragma unroll
        for (int i = 0; i < 4; ++i) {
            int c = tid + i * 256;
            int row = c >> 3, kq = c & 7;
            const __half* src = Bg + (size_t)row * K + k0 + kq * 8;
            unsigned dst = (unsigned)__cvta_generic_to_shared(
                Bs + row * S_STRIDE + kq * 8);
            asm volatile("cp.async.cg.shared.global [%0], [%1], 16;\n"
                         :: "r"(dst), "l"(src));
        }
        asm volatile("cp.async.commit_group;\n");
    };

    float acc[4][4][4];
    #pragma unroll
    for (int mt = 0; mt < 4; ++mt)
        #pragma unroll
        for (int nt = 0; nt < 4; ++nt)
            #pragma unroll
            for (int r = 0; r < 4; ++r) acc[mt][nt][r] = 0.0f;

    const int KT = K / BK;
    issue_tile(0, 0);
    issue_tile(1, 1);

    for (int kt = 0; kt < KT; ++kt) {
        // Tile kt must be resident. Newest group in flight is tile kt+1
        // (tile kt+2 is issued only after the barrier), so allow 1 pending
        // group except on the last iteration.
        if (kt + 1 < KT) asm volatile("cp.async.wait_group 1;\n" ::: "memory");
        else             asm volatile("cp.async.wait_group 0;\n" ::: "memory");
        // Single barrier: (a) tile kt visible to all warps, (b) all warps
        // finished reading stage (kt-1)%3 == (kt+2)%3 in iteration kt-1,
        // making it safe to overwrite below.
        __syncthreads();
        if (kt + 2 < KT) issue_tile(kt + 2, (kt + 2) % STAGES);

        const unsigned as_u32 = smem_u32 + (kt % STAGES) * STAGE_B;
        const unsigned bs_u32 = as_u32 + AS_H * 2;
        const unsigned a_base = as_u32 +
            ((warp_m * 64 + a_lrow) * S_STRIDE + a_lk8) * 2;
        const unsigned b_base = bs_u32 +
            ((warp_n * 32 + b_lrow) * S_STRIDE + b_lk8) * 2;

        #pragma unroll
        for (int ks = 0; ks < 4; ++ks) {          // 4 x k16 steps
            const unsigned kofs = ks * 32;        // 16 halves = 32 B
            // B fragments first (every MMA needs them)
            unsigned bf[4][2];
            ldsm_x4(bf[0][0], bf[0][1], bf[1][0], bf[1][1], b_base + kofs);
            ldsm_x4(bf[2][0], bf[2][1], bf[3][0], bf[3][1],
                    b_base + 16 * S_STRIDE * 2 + kofs);
            // A pipelined across mt: ldsm af[mt+1] before MMAs on af[mt]
            unsigned af[4][4];
            ldsm_x4(af[0][0], af[0][1], af[0][2], af[0][3], a_base + kofs);
            #pragma unroll
            for (int mt = 0; mt < 4; ++mt) {
                if (mt < 3)
                    ldsm_x4(af[mt+1][0], af[mt+1][1], af[mt+1][2], af[mt+1][3],
                            a_base + (mt + 1) * 16 * S_STRIDE * 2 + kofs);
                #pragma unroll
                for (int nt = 0; nt < 4; ++nt) {
                    asm volatile(
                        "mma.sync.aligned.m16n8k16.row.col.f32.f16.f16.f32 "
                        "{%0,%1,%2,%3}, {%4,%5,%6,%7}, {%8,%9}, {%0,%1,%2,%3};\n"
                        : "+f"(acc[mt][nt][0]), "+f"(acc[mt][nt][1]),
                          "+f"(acc[mt][nt][2]), "+f"(acc[mt][nt][3])
                        : "r"(af[mt][0]), "r"(af[mt][1]),
                          "r"(af[mt][2]), "r"(af[mt][3]),
                          "r"(bf[nt][0]), "r"(bf[nt][1]));
                }
            }
        }
    }

    // Epilogue (no barrier needed: acc in regs, smem not reused)
    #pragma unroll
    for (int mt = 0; mt < 4; ++mt) {
        const int r0 = m_cta + warp_m * 64 + mt * 16 + g;
        #pragma unroll
        for (int nt = 0; nt < 4; ++nt) {
            const int col = n_cta + warp_n * 32 + nt * 8 + tg * 2;
            const float bv0 = bias[col], bv1 = bias[col + 1];
            float v0 = acc[mt][nt][0] + bv0;
            float v1 = acc[mt][nt][1] + bv1;
            float v2 = acc[mt][nt][2] + bv0;
            float v3 = acc[mt][nt][3] + bv1;
            if (FUSED) {
                __half* C = reinterpret_cast<__half*>(Cv);
                *reinterpret_cast<__half2*>(C + (size_t)r0 * N + col) =
                    __floats2half2_rn(fmaxf(v0, 0.0f), fmaxf(v1, 0.0f));
                *reinterpret_cast<__half2*>(C + (size_t)(r0 + 8) * N + col) =
                    __floats2half2_rn(fmaxf(v2, 0.0f), fmaxf(v3, 0.0f));
            } else {
                float* C = reinterpret_cast<float*>(Cv);
                *reinterpret_cast<float2*>(C + (size_t)r0 * N + col) =
                    make_float2(v0, v1);
                *reinterpret_cast<float2*>(C + (size_t)(r0 + 8) * N + col) =
                    make_float2(v2, v3);
            }
        }
    }
}

// ---------------------------------------------------------------------------
// Launch
// ---------------------------------------------------------------------------
extern "C" void kernel_launch(void* const* d_in, const int* in_sizes, int n_in,
                              void* d_out, int out_size)
{
    (void)in_sizes; (void)n_in; (void)out_size;
    const float* emb = (const float*)d_in[0];
    const float* W1  = (const float*)d_in[1];
    const float* b1  = (const float*)d_in[2];
    const float* W2  = (const float*)d_in[3];
    const float* b2  = (const float*)d_in[4];
    float* out = (float*)d_out;

    cudaFuncSetAttribute(gemm_fp16<true>,
                         cudaFuncAttributeMaxDynamicSharedMemorySize, SMEM_BYTES);
    cudaFuncSetAttribute(gemm_fp16<false>,
                         cudaFuncAttributeMaxDynamicSharedMemorySize, SMEM_BYTES);

    void *pA = nullptr, *pH = nullptr, *pW1 = nullptr, *pW2 = nullptr;
    cudaGetSymbolAddress(&pA, g_agg);
    cudaGetSymbolAddress(&pH, g_hid);
    cudaGetSymbolAddress(&pW1, g_w1t);
    cudaGetSymbolAddress(&pW2, g_w2t);
    __half* agg = (__half*)pA;
    __half* hid = (__half*)pH;
    __half* w1t = (__half*)pW1;
    __half* w2t = (__half*)pW2;

    // 1) Aggregation -> fp16: (4, 8192, 1024)
    agg_kernel<<<B_N * (D_DIM / 4) / 256, 256>>>(emb);

    // 1b) Weights -> [N,K] fp16
    transpose_half<<<dim3(H_DIM / 32, D_DIM / 32), dim3(32, 8)>>>(
        W1, w1t, D_DIM, H_DIM);   // W1 [D,H] -> w1t [H,D]
    transpose_half<<<dim3(D_DIM / 32, H_DIM / 32), dim3(32, 8)>>>(
        W2, w2t, H_DIM, D_DIM);   // W2 [H,D] -> w2t [D,H]

    // 2) hid = fp16(relu(agg @ W1 + b1)): M=32768, N=4096, K=1024
    {
        dim3 grid(H_DIM / BN, M_TOT / BM);   // (32, 256)
        gemm_fp16<true><<<grid, 256, SMEM_BYTES>>>(agg, w1t, b1, hid,
                                                   M_TOT, H_DIM, D_DIM);
    }

    // 3) out = hid @ W2 + b2: M=32768, N=1024, K=4096 -> (4,8192,1024)
    {
        dim3 grid(D_DIM / BN, M_TOT / BM);   // (8, 256)
        gemm_fp16<false><<<grid, 256, SMEM_BYTES>>>(hid, w2t, b2, out,
                                                    M_TOT, D_DIM, H_DIM);
    }
}